// round 2
// baseline (speedup 1.0000x reference)
#include <cuda_runtime.h>
#include <cstddef>

#define Hdim 1024
#define NHnum 16
#define DHdim 64
#define Bb 4
#define Tfull 1024
#define DINc 2304
#define Ff 4096
#define HH (1024*1024)

// ------------------------- scratch (device globals) -------------------------
__device__ float g_xT [(size_t)Bb*Tfull*DINc];
__device__ float g_wTe[(size_t)3*DINc*Hdim];
__device__ float g_wTc[(size_t)3*Hdim*Hdim];
__device__ float g_wTd[(size_t)3*3*Hdim*Hdim];
__device__ float g_bufX [(size_t)Bb*Tfull*Hdim];
__device__ float g_bufQ [(size_t)Bb*Tfull*Hdim];
__device__ float g_bufK [(size_t)Bb*Tfull*Hdim];
__device__ float g_bufV [(size_t)Bb*Tfull*Hdim];
__device__ float g_bufA [(size_t)Bb*Tfull*Hdim];
__device__ float g_bufT [(size_t)Bb*Tfull*Hdim];
__device__ float g_bufY [(size_t)Bb*Tfull*Hdim];
__device__ float g_bufD [(size_t)Bb*Tfull*Hdim];
__device__ float g_bufY2[(size_t)Bb*Tfull*Hdim];
__device__ float g_bufZ [(size_t)Bb*Tfull*Hdim];
__device__ float g_bufF [(size_t)Bb*Tfull*Ff];

// ------------------------- transposes -------------------------
__global__ void transpose2d_kernel(float* __restrict__ dst, const float* __restrict__ src,
                                   int R, int C)
{
    __shared__ float tile[32][33];
    int b = blockIdx.z;
    const float* s = src + (size_t)b * R * C;
    float* d = dst + (size_t)b * R * C;
    int c0 = blockIdx.x * 32, r0 = blockIdx.y * 32;
    int tx = threadIdx.x, ty = threadIdx.y;
    #pragma unroll
    for (int i = 0; i < 32; i += 8)
        tile[ty + i][tx] = s[(size_t)(r0 + ty + i) * C + c0 + tx];
    __syncthreads();
    #pragma unroll
    for (int i = 0; i < 32; i += 8)
        d[(size_t)(c0 + ty + i) * R + r0 + tx] = tile[tx][ty + i];
}

// conv weight (Hout, Cin, 3) -> (3, Cin, Hout)
__global__ void transpose_convw_kernel(float* __restrict__ dst, const float* __restrict__ src,
                                       int Hout, int Cin)
{
    __shared__ float tile[32][33];
    int k = blockIdx.z;
    int c0 = blockIdx.x * 32, h0 = blockIdx.y * 32;
    int tx = threadIdx.x, ty = threadIdx.y;
    #pragma unroll
    for (int i = 0; i < 32; i += 8)
        tile[tx][ty + i] = src[((size_t)(h0 + ty + i) * Cin + c0 + tx) * 3 + k];
    __syncthreads();
    #pragma unroll
    for (int i = 0; i < 32; i += 8)
        dst[((size_t)k * Cin + c0 + ty + i) * Hout + h0 + tx] = tile[ty + i][tx];
}

// dec_deconv_w (3, Hin, Hout, 3k) -> (3 layers)(3k, Hin, Hout); flip folded into gather
__global__ void transpose_deconvw_kernel(float* __restrict__ dst, const float* __restrict__ src)
{
    int idx = blockIdx.x * 256 + threadIdx.x;
    int o  = idx & 1023;
    int r  = idx >> 10;
    int ii = r & 1023;
    int ik = r >> 10;
    int i = ik / 3, k = ik - i * 3;
    dst[idx] = src[(size_t)i * 3 * HH + ((size_t)ii * 1024 + o) * 3 + k];
}

// ------------------------- SGEMM C(M,N) = A(M,K) @ B(K,N) [+bias][relu] -----
__global__ __launch_bounds__(256, 2) void sgemm_kernel(
    const float* __restrict__ A, const float* __restrict__ B, float* __restrict__ C,
    int M, int N, int K, const float* __restrict__ bias, int relu)
{
    __shared__ float As[16][128];
    __shared__ float Bs[16][128];
    const int tid = threadIdx.x;
    const int bx = blockIdx.x, by = blockIdx.y;
    const int tx = tid & 15, ty = tid >> 4;
    const int aRow = tid >> 2;
    const int aCol = (tid & 3) << 2;
    const int bRow = tid >> 5;
    const int bCol = (tid & 31) << 2;
    const float* Ab = A + (size_t)by * 128 * K;
    const float* Bp = B + (size_t)bx * 128;
    float acc[8][8];
    #pragma unroll
    for (int i = 0; i < 8; i++)
        #pragma unroll
        for (int j = 0; j < 8; j++) acc[i][j] = 0.f;

    for (int k0 = 0; k0 < K; k0 += 16) {
        #pragma unroll
        for (int i = 0; i < 2; i++) {
            float4 va = *(const float4*)(Ab + (size_t)(aRow + i * 64) * K + k0 + aCol);
            As[aCol + 0][aRow + i * 64] = va.x;
            As[aCol + 1][aRow + i * 64] = va.y;
            As[aCol + 2][aRow + i * 64] = va.z;
            As[aCol + 3][aRow + i * 64] = va.w;
            *(float4*)&Bs[bRow + i * 8][bCol] =
                *(const float4*)(Bp + (size_t)(k0 + bRow + i * 8) * N + bCol);
        }
        __syncthreads();
        #pragma unroll
        for (int kk = 0; kk < 16; kk++) {
            float ar[8], br[8];
            *(float4*)&ar[0] = *(const float4*)&As[kk][ty * 8];
            *(float4*)&ar[4] = *(const float4*)&As[kk][ty * 8 + 4];
            *(float4*)&br[0] = *(const float4*)&Bs[kk][tx * 8];
            *(float4*)&br[4] = *(const float4*)&Bs[kk][tx * 8 + 4];
            #pragma unroll
            for (int i = 0; i < 8; i++)
                #pragma unroll
                for (int j = 0; j < 8; j++)
                    acc[i][j] += ar[i] * br[j];
        }
        __syncthreads();
    }
    const int row0 = by * 128 + ty * 8;
    const int col0 = bx * 128 + tx * 8;
    float bv[8];
    #pragma unroll
    for (int j = 0; j < 8; j++) bv[j] = bias ? bias[col0 + j] : 0.f;
    #pragma unroll
    for (int i = 0; i < 8; i++) {
        float v[8];
        #pragma unroll
        for (int j = 0; j < 8; j++) {
            v[j] = acc[i][j] + bv[j];
            if (relu) v[j] = fmaxf(v[j], 0.f);
        }
        *(float4*)(C + (size_t)(row0 + i) * N + col0)     = make_float4(v[0], v[1], v[2], v[3]);
        *(float4*)(C + (size_t)(row0 + i) * N + col0 + 4) = make_float4(v[4], v[5], v[6], v[7]);
    }
}

// --------------- conv/deconv as gather-A GEMM -------------------------------
// mode 0 (conv k=3,pad=1,s=1): tin = t + kseg - 1
// mode 1 (deconv k=3,pad=1,outpad=s-1): tin = (t+1-kseg)/s when >=0 and divisible
__global__ __launch_bounds__(256, 2) void convgemm_kernel(
    const float* __restrict__ In, const float* __restrict__ Wt, float* __restrict__ C,
    int Tout, int Tin, int Cin, int N, int stride, int mode,
    const float* __restrict__ bias, int relu)
{
    __shared__ float As[16][128];
    __shared__ float Bs[16][128];
    const int tid = threadIdx.x;
    const int bx = blockIdx.x, by = blockIdx.y;
    const int tx = tid & 15, ty = tid >> 4;
    const int aRow = tid >> 2;
    const int aCol = (tid & 3) << 2;
    const int bRow = tid >> 5;
    const int bCol = (tid & 31) << 2;
    const int K = 3 * Cin;
    float acc[8][8];
    #pragma unroll
    for (int i = 0; i < 8; i++)
        #pragma unroll
        for (int j = 0; j < 8; j++) acc[i][j] = 0.f;

    for (int k0 = 0; k0 < K; k0 += 16) {
        #pragma unroll
        for (int i = 0; i < 2; i++) {
            int m = by * 128 + aRow + i * 64;
            int bb = m / Tout, t = m - bb * Tout;
            int kk = k0 + aCol;
            int kseg = kk / Cin, c = kk - kseg * Cin;
            float4 va = make_float4(0.f, 0.f, 0.f, 0.f);
            if (mode == 0) {
                int tin = t + kseg - 1;
                if (tin >= 0 && tin < Tin)
                    va = *(const float4*)(In + ((size_t)(bb * Tin + tin) * Cin + c));
            } else {
                int num = t + 1 - kseg;
                if (num >= 0 && (num % stride) == 0) {
                    int tin = num / stride;
                    if (tin < Tin)
                        va = *(const float4*)(In + ((size_t)(bb * Tin + tin) * Cin + c));
                }
            }
            As[aCol + 0][aRow + i * 64] = va.x;
            As[aCol + 1][aRow + i * 64] = va.y;
            As[aCol + 2][aRow + i * 64] = va.z;
            As[aCol + 3][aRow + i * 64] = va.w;
            *(float4*)&Bs[bRow + i * 8][bCol] =
                *(const float4*)(Wt + (size_t)(k0 + bRow + i * 8) * N + bx * 128 + bCol);
        }
        __syncthreads();
        #pragma unroll
        for (int kk = 0; kk < 16; kk++) {
            float ar[8], br[8];
            *(float4*)&ar[0] = *(const float4*)&As[kk][ty * 8];
            *(float4*)&ar[4] = *(const float4*)&As[kk][ty * 8 + 4];
            *(float4*)&br[0] = *(const float4*)&Bs[kk][tx * 8];
            *(float4*)&br[4] = *(const float4*)&Bs[kk][tx * 8 + 4];
            #pragma unroll
            for (int i = 0; i < 8; i++)
                #pragma unroll
                for (int j = 0; j < 8; j++)
                    acc[i][j] += ar[i] * br[j];
        }
        __syncthreads();
    }
    const int row0 = by * 128 + ty * 8;
    const int col0 = bx * 128 + tx * 8;
    float bv[8];
    #pragma unroll
    for (int j = 0; j < 8; j++) bv[j] = bias ? bias[col0 + j] : 0.f;
    #pragma unroll
    for (int i = 0; i < 8; i++) {
        float v[8];
        #pragma unroll
        for (int j = 0; j < 8; j++) {
            v[j] = acc[i][j] + bv[j];
            if (relu) v[j] = fmaxf(v[j], 0.f);
        }
        *(float4*)(C + (size_t)(row0 + i) * N + col0)     = make_float4(v[0], v[1], v[2], v[3]);
        *(float4*)(C + (size_t)(row0 + i) * N + col0 + 4) = make_float4(v[4], v[5], v[6], v[7]);
    }
}

// ------------------------- fused attention ----------------------------------
// grid (Sq/128, NH, B), 128 threads, online softmax over 128-row KV blocks.
// windowed=1: only own block (encoder block-diagonal MS=128 mask, exact).
__global__ __launch_bounds__(128) void attn_kernel(
    const float* __restrict__ Q, const float* __restrict__ Kk, const float* __restrict__ V,
    float* __restrict__ O, int S, int windowed)
{
    extern __shared__ float sm[];
    float* Ks = sm;
    float* Vs = sm + 8192;
    float* Sc = sm + 16384;
    const int tid = threadIdx.x;
    const int qb = blockIdx.x, h = blockIdx.y, b = blockIdx.z;
    const int qi = qb * 128 + tid;
    const float* qp = Q + (((size_t)(b * S + qi)) * NHnum + h) * DHdim;
    float qv[64];
    #pragma unroll
    for (int d4 = 0; d4 < 16; d4++) {
        float4 v = *(const float4*)(qp + d4 * 4);
        qv[d4 * 4 + 0] = v.x; qv[d4 * 4 + 1] = v.y;
        qv[d4 * 4 + 2] = v.z; qv[d4 * 4 + 3] = v.w;
    }
    float acc[64];
    #pragma unroll
    for (int d = 0; d < 64; d++) acc[d] = 0.f;
    float mrow = -1e30f, lrow = 0.f;
    const int jb0 = windowed ? qb : 0;
    const int jb1 = windowed ? qb + 1 : (S >> 7);
    for (int jb = jb0; jb < jb1; jb++) {
        const float* kp = Kk + (((size_t)(b * S + jb * 128)) * NHnum + h) * DHdim;
        const float* vp = V  + (((size_t)(b * S + jb * 128)) * NHnum + h) * DHdim;
        #pragma unroll 4
        for (int i = tid; i < 2048; i += 128) {
            int r = i >> 4, c = i & 15;
            *(float4*)&Ks[r * 64 + c * 4] = *(const float4*)(kp + (size_t)r * Hdim + c * 4);
            *(float4*)&Vs[r * 64 + c * 4] = *(const float4*)(vp + (size_t)r * Hdim + c * 4);
        }
        __syncthreads();
        float bmax = -1e30f;
        for (int j = 0; j < 128; j++) {
            const float4* kr = (const float4*)(Ks + j * 64);
            float s0 = 0.f, s1 = 0.f, s2 = 0.f, s3 = 0.f;
            #pragma unroll
            for (int d4 = 0; d4 < 16; d4++) {
                float4 kv = kr[d4];
                s0 += qv[d4 * 4 + 0] * kv.x; s1 += qv[d4 * 4 + 1] * kv.y;
                s2 += qv[d4 * 4 + 2] * kv.z; s3 += qv[d4 * 4 + 3] * kv.w;
            }
            float sres = ((s0 + s1) + (s2 + s3)) * 0.125f;
            Sc[j * 128 + tid] = sres;
            bmax = fmaxf(bmax, sres);
        }
        float nm = fmaxf(mrow, bmax);
        float corr = __expf(mrow - nm);
        lrow *= corr;
        #pragma unroll
        for (int d = 0; d < 64; d++) acc[d] *= corr;
        for (int j = 0; j < 128; j++) {
            float p = __expf(Sc[j * 128 + tid] - nm);
            lrow += p;
            const float4* vr = (const float4*)(Vs + j * 64);
            #pragma unroll
            for (int d4 = 0; d4 < 16; d4++) {
                float4 vv = vr[d4];
                acc[d4 * 4 + 0] += p * vv.x; acc[d4 * 4 + 1] += p * vv.y;
                acc[d4 * 4 + 2] += p * vv.z; acc[d4 * 4 + 3] += p * vv.w;
            }
        }
        mrow = nm;
        __syncthreads();
    }
    const float invl = 1.f / lrow;
    float* op = O + (((size_t)(b * S + qi)) * NHnum + h) * DHdim;
    #pragma unroll
    for (int d4 = 0; d4 < 16; d4++)
        *(float4*)(op + d4 * 4) = make_float4(acc[d4 * 4 + 0] * invl, acc[d4 * 4 + 1] * invl,
                                              acc[d4 * 4 + 2] * invl, acc[d4 * 4 + 3] * invl);
}

// ------------------------- LayerNorm(in1 + in2) ------------------------------
__global__ __launch_bounds__(256) void ln_kernel(
    float* __restrict__ out, const float* __restrict__ in1, const float* __restrict__ in2,
    const float* __restrict__ g, const float* __restrict__ be)
{
    __shared__ float rs[8], rss[8];
    const int row = blockIdx.x, tid = threadIdx.x;
    const size_t base = (size_t)row * Hdim + tid * 4;
    float4 a = *(const float4*)(in1 + base);
    float4 b2 = *(const float4*)(in2 + base);
    a.x += b2.x; a.y += b2.y; a.z += b2.z; a.w += b2.w;
    float s  = a.x + a.y + a.z + a.w;
    float ss = a.x * a.x + a.y * a.y + a.z * a.z + a.w * a.w;
    #pragma unroll
    for (int o = 16; o > 0; o >>= 1) {
        s  += __shfl_xor_sync(0xffffffffu, s, o);
        ss += __shfl_xor_sync(0xffffffffu, ss, o);
    }
    if ((tid & 31) == 0) { rs[tid >> 5] = s; rss[tid >> 5] = ss; }
    __syncthreads();
    float st = 0.f, sst = 0.f;
    #pragma unroll
    for (int i = 0; i < 8; i++) { st += rs[i]; sst += rss[i]; }
    const float mean = st * (1.f / 1024.f);
    const float var  = sst * (1.f / 1024.f) - mean * mean;
    const float inv  = rsqrtf(var + 1e-5f);
    float4 gg = *(const float4*)(g + tid * 4);
    float4 bb = *(const float4*)(be + tid * 4);
    float4 o4;
    o4.x = (a.x - mean) * inv * gg.x + bb.x;
    o4.y = (a.y - mean) * inv * gg.y + bb.y;
    o4.z = (a.z - mean) * inv * gg.z + bb.z;
    o4.w = (a.w - mean) * inv * gg.w + bb.w;
    *(float4*)(out + base) = o4;
}

// ------------------------- pool / add ---------------------------------------
__global__ void poolrelu_kernel(float* __restrict__ out, const float* __restrict__ in,
                                int S2, int n4)
{
    int idx = blockIdx.x * blockDim.x + threadIdx.x;
    if (idx >= n4) return;
    int h4 = idx & 255;
    int bt = idx >> 8;
    int b = bt / S2, t2 = bt - b * S2;
    const float4* i0 = (const float4*)in + ((size_t)(b * S2 * 2 + t2 * 2) * 256 + h4);
    float4 a = i0[0], c = i0[256];
    float4 o;
    o.x = fmaxf(fmaxf(a.x, c.x), 0.f);
    o.y = fmaxf(fmaxf(a.y, c.y), 0.f);
    o.z = fmaxf(fmaxf(a.z, c.z), 0.f);
    o.w = fmaxf(fmaxf(a.w, c.w), 0.f);
    ((float4*)out)[idx] = o;
}

__global__ void add_kernel(float* __restrict__ out, const float* __restrict__ a,
                           const float* __restrict__ b, int n4)
{
    int i = blockIdx.x * blockDim.x + threadIdx.x;
    if (i >= n4) return;
    float4 x = ((const float4*)a)[i], y = ((const float4*)b)[i];
    ((float4*)out)[i] = make_float4(x.x + y.x, x.y + y.y, x.z + y.z, x.w + y.w);
}

// ------------------------- host orchestration -------------------------------
static inline void sgemm(const float* A, const float* B, float* C, int M, int N, int K,
                         const float* bias, int relu)
{
    dim3 g(N / 128, M / 128);
    sgemm_kernel<<<g, 256>>>(A, B, C, M, N, K, bias, relu);
}

extern "C" void kernel_launch(void* const* d_in, const int* in_sizes, int n_in,
                              void* d_out, int out_size)
{
    (void)in_sizes; (void)n_in; (void)out_size;
    const float* x          = (const float*)d_in[0];
    const float* emb_w      = (const float*)d_in[1];
    const float* emb_b      = (const float*)d_in[2];
    const float* enc_qkvo   = (const float*)d_in[3];
    const float* enc_ln     = (const float*)d_in[4];
    const float* enc_ffn_w1 = (const float*)d_in[5];
    const float* enc_ffn_b1 = (const float*)d_in[6];
    const float* enc_ffn_w2 = (const float*)d_in[7];
    const float* enc_ffn_b2 = (const float*)d_in[8];
    const float* conv0_w    = (const float*)d_in[9];
    const float* conv0_b    = (const float*)d_in[10];
    const float* dec_qkvo0  = (const float*)d_in[11];
    const float* dec_ln0    = (const float*)d_in[12];
    const float* dec_attn1  = (const float*)d_in[13];
    const float* dec_attn2  = (const float*)d_in[14];
    const float* dec_ln     = (const float*)d_in[15];
    const float* dec_ffn_w1 = (const float*)d_in[16];
    const float* dec_ffn_b1 = (const float*)d_in[17];
    const float* dec_ffn_w2 = (const float*)d_in[18];
    const float* dec_ffn_b2 = (const float*)d_in[19];
    const float* dec_dw     = (const float*)d_in[20];
    const float* dec_db     = (const float*)d_in[21];

    float *xT, *wTe, *wTc, *wTd, *bX, *bQ, *bK, *bV, *bA, *bT, *bY, *bD, *bY2, *bZ, *bF;
    cudaGetSymbolAddress((void**)&xT,  g_xT);
    cudaGetSymbolAddress((void**)&wTe, g_wTe);
    cudaGetSymbolAddress((void**)&wTc, g_wTc);
    cudaGetSymbolAddress((void**)&wTd, g_wTd);
    cudaGetSymbolAddress((void**)&bX,  g_bufX);
    cudaGetSymbolAddress((void**)&bQ,  g_bufQ);
    cudaGetSymbolAddress((void**)&bK,  g_bufK);
    cudaGetSymbolAddress((void**)&bV,  g_bufV);
    cudaGetSymbolAddress((void**)&bA,  g_bufA);
    cudaGetSymbolAddress((void**)&bT,  g_bufT);
    cudaGetSymbolAddress((void**)&bY,  g_bufY);
    cudaGetSymbolAddress((void**)&bD,  g_bufD);
    cudaGetSymbolAddress((void**)&bY2, g_bufY2);
    cudaGetSymbolAddress((void**)&bZ,  g_bufZ);
    cudaGetSymbolAddress((void**)&bF,  g_bufF);

    float* out = (float*)d_out;
    // output segment offsets (floats): Z0,Z1,Z2,Z3,fd0,fd1,fd2,fd3
    float* Z0  = out;
    float* Z1  = out + (size_t)4194304;
    float* Z2  = out + (size_t)8388608;
    float* Z3  = out + (size_t)10485760;
    float* FD0 = out + (size_t)11534336;
    float* FD1 = out + (size_t)12582912;
    float* FD2 = out + (size_t)14680064;
    float* FD3 = out + (size_t)18874368;

    static int smem_set = 0;
    if (!smem_set) {
        cudaFuncSetAttribute(attn_kernel, cudaFuncAttributeMaxDynamicSharedMemorySize, 131072);
        smem_set = 1;
    }

    // ---- transposes ----
    {
        dim3 blk(32, 8);
        transpose2d_kernel    <<<dim3(Tfull/32, DINc/32, Bb), blk>>>(xT, x, DINc, Tfull);
        transpose_convw_kernel<<<dim3(DINc/32, Hdim/32, 3),   blk>>>(wTe, emb_w, Hdim, DINc);
        transpose_convw_kernel<<<dim3(Hdim/32, Hdim/32, 3),   blk>>>(wTc, conv0_w, Hdim, Hdim);
        transpose_deconvw_kernel<<<(3*3*HH)/256, 256>>>(wTd, dec_dw);
    }

    // ---- embedding conv + relu: (B,T,DIN) -> bX (B,T,H) ----
    convgemm_kernel<<<dim3(Hdim/128, (Bb*Tfull)/128), 256>>>(
        xT, wTe, bX, Tfull, Tfull, DINc, Hdim, 1, 0, emb_b, 1);

    // ---- MHA helper (host lambda) ----
    auto mha = [&](const float* xq, const float* xkv, const float* w, int S, int windowed) {
        int rows = Bb * S;
        sgemm(xq,  w + 0*(size_t)HH, bQ, rows, Hdim, Hdim, nullptr, 0);
        sgemm(xkv, w + 1*(size_t)HH, bK, rows, Hdim, Hdim, nullptr, 0);
        sgemm(xkv, w + 2*(size_t)HH, bV, rows, Hdim, Hdim, nullptr, 0);
        attn_kernel<<<dim3(S/128, NHnum, Bb), 128, 131072>>>(bQ, bK, bV, bA, S, windowed);
        sgemm(bA, w + 3*(size_t)HH, bT, rows, Hdim, Hdim, nullptr, 0);  // -> bT
    };

    // ================= encoder =================
    const int encS[4] = {1024, 1024, 512, 256};
    float* Zp[4] = {Z0, Z1, Z2, Z3};
    for (int i = 0; i < 4; i++) {
        int S = encS[i], rows = Bb * S;
        const float* w = enc_qkvo + (size_t)i * 4 * HH;
        mha(bX, bX, w, S, 1);
        const float* lnb = enc_ln + (size_t)i * 4 * Hdim;
        ln_kernel<<<rows, 256>>>(bY, bX, bT, lnb + 0*Hdim, lnb + 1*Hdim);
        sgemm(bY, enc_ffn_w1 + (size_t)i*Hdim*Ff, bF, rows, Ff, Hdim,
              enc_ffn_b1 + (size_t)i*Ff, 1);
        sgemm(bF, enc_ffn_w2 + (size_t)i*Ff*Hdim, bT, rows, Hdim, Ff,
              enc_ffn_b2 + (size_t)i*Hdim, 0);
        ln_kernel<<<rows, 256>>>(Zp[i], bY, bT, lnb + 2*Hdim, lnb + 3*Hdim);
        if (i == 0) {
            convgemm_kernel<<<dim3(Hdim/128, rows/128), 256>>>(
                Zp[i], wTc, bX, S, S, Hdim, Hdim, 1, 0, conv0_b, 1);
        } else if (i < 3) {
            int S2 = S / 2, n4 = Bb * S2 * (Hdim/4);
            poolrelu_kernel<<<(n4 + 255)/256, 256>>>(bX, Zp[i], S2, n4);
        }
    }

    // ================= decoder level 0 (self-attn on Z3, S=256) =================
    {
        int S = 256, rows = Bb * S;
        mha(Z3, Z3, dec_qkvo0, S, 0);
        ln_kernel<<<rows, 256>>>(FD0, Z3, bT, dec_ln0, dec_ln0 + Hdim);
    }

    // ================= decoder levels =================
    const float* fdPrev = FD0; int Sprev = 256;
    const float* feP[3] = {Z2, Z1, Z0};
    const int    decS[3] = {512, 1024, 1024};
    const int    decStride[3] = {2, 2, 1};
    float* fdOut[3] = {FD1, FD2, FD3};
    for (int i = 0; i < 3; i++) {
        int S = decS[i], rows = Bb * S, st = decStride[i];
        // deconv + relu: fdPrev (B,Sprev,H) -> bD (B,S,H)
        convgemm_kernel<<<dim3(Hdim/128, rows/128), 256>>>(
            fdPrev, wTd + (size_t)i*3*HH, bD, S, Sprev, Hdim, Hdim, st, 1,
            dec_db + (size_t)i*Hdim, 1);
        const float* a1 = dec_attn1 + (size_t)i * 4 * HH;
        const float* a2 = dec_attn2 + (size_t)i * 4 * HH;
        const float* lnb = dec_ln + (size_t)i * 6 * Hdim;
        // X2 = LN(fe + mha(fe, fd))
        mha(feP[i], bD, a1, S, 0);
        ln_kernel<<<rows, 256>>>(bY, feP[i], bT, lnb + 0*Hdim, lnb + 1*Hdim);
        // Y2 = LN(fd + mha(fd, fe))
        mha(bD, feP[i], a2, S, 0);
        ln_kernel<<<rows, 256>>>(bY2, bD, bT, lnb + 2*Hdim, lnb + 3*Hdim);
        // Zd = X2 + Y2
        int n4 = rows * (Hdim/4);
        add_kernel<<<(n4 + 255)/256, 256>>>(bZ, bY, bY2, n4);
        // fd = LN(Zd + ffn(Zd))
        sgemm(bZ, dec_ffn_w1 + (size_t)i*Hdim*Ff, bF, rows, Ff, Hdim,
              dec_ffn_b1 + (size_t)i*Ff, 1);
        sgemm(bF, dec_ffn_w2 + (size_t)i*Ff*Hdim, bT, rows, Hdim, Ff,
              dec_ffn_b2 + (size_t)i*Hdim, 0);
        ln_kernel<<<rows, 256>>>(fdOut[i], bZ, bT, lnb + 4*Hdim, lnb + 5*Hdim);
        fdPrev = fdOut[i]; Sprev = S;
    }
}

// round 3
// speedup vs baseline: 1.2714x; 1.2714x over previous
#include <cuda_runtime.h>
#include <cstddef>
#include <cstdint>

#define Hdim 1024
#define NHnum 16
#define DHdim 64
#define Bb 4
#define Tfull 1024
#define DINc 2304
#define Ff 4096
#define HH (1024*1024)

// ------------------------- scratch (device globals) -------------------------
__device__ float g_xT [(size_t)Bb*Tfull*DINc];
__device__ float g_wTe[(size_t)3*DINc*Hdim];
__device__ float g_wTc[(size_t)3*Hdim*Hdim];
__device__ float g_wTd[(size_t)3*3*Hdim*Hdim];
__device__ float g_bufX [(size_t)Bb*Tfull*Hdim];
__device__ float g_bufQ [(size_t)Bb*Tfull*Hdim];
__device__ float g_bufK [(size_t)Bb*Tfull*Hdim];
__device__ float g_bufV [(size_t)Bb*Tfull*Hdim];
__device__ float g_bufA [(size_t)Bb*Tfull*Hdim];
__device__ float g_bufT [(size_t)Bb*Tfull*Hdim];
__device__ float g_bufY [(size_t)Bb*Tfull*Hdim];
__device__ float g_bufD [(size_t)Bb*Tfull*Hdim];
__device__ float g_bufY2[(size_t)Bb*Tfull*Hdim];
__device__ float g_bufZ [(size_t)Bb*Tfull*Hdim];
__device__ float g_bufF [(size_t)Bb*Tfull*Ff];

// ------------------------- transposes -------------------------
__global__ void transpose2d_kernel(float* __restrict__ dst, const float* __restrict__ src,
                                   int R, int C)
{
    __shared__ float tile[32][33];
    int b = blockIdx.z;
    const float* s = src + (size_t)b * R * C;
    float* d = dst + (size_t)b * R * C;
    int c0 = blockIdx.x * 32, r0 = blockIdx.y * 32;
    int tx = threadIdx.x, ty = threadIdx.y;
    #pragma unroll
    for (int i = 0; i < 32; i += 8)
        tile[ty + i][tx] = s[(size_t)(r0 + ty + i) * C + c0 + tx];
    __syncthreads();
    #pragma unroll
    for (int i = 0; i < 32; i += 8)
        d[(size_t)(c0 + ty + i) * R + r0 + tx] = tile[tx][ty + i];
}

__global__ void transpose_convw_kernel(float* __restrict__ dst, const float* __restrict__ src,
                                       int Hout, int Cin)
{
    __shared__ float tile[32][33];
    int k = blockIdx.z;
    int c0 = blockIdx.x * 32, h0 = blockIdx.y * 32;
    int tx = threadIdx.x, ty = threadIdx.y;
    #pragma unroll
    for (int i = 0; i < 32; i += 8)
        tile[tx][ty + i] = src[((size_t)(h0 + ty + i) * Cin + c0 + tx) * 3 + k];
    __syncthreads();
    #pragma unroll
    for (int i = 0; i < 32; i += 8)
        dst[((size_t)k * Cin + c0 + ty + i) * Hout + h0 + tx] = tile[ty + i][tx];
}

__global__ void transpose_deconvw_kernel(float* __restrict__ dst, const float* __restrict__ src)
{
    int idx = blockIdx.x * 256 + threadIdx.x;
    int o  = idx & 1023;
    int r  = idx >> 10;
    int ii = r & 1023;
    int ik = r >> 10;
    int i = ik / 3, k = ik - i * 3;
    dst[idx] = src[(size_t)i * 3 * HH + ((size_t)ii * 1024 + o) * 3 + k];
}

// ===================== 3xTF32 tensor-core GEMM =====================
// C(M,N) = A(M,K) @ B(K,N) [+bias][relu].  Tile 128x128x32, 256 threads,
// 8 warps (2 M x 4 N), per-warp 64x32 via 4x4 m16n8k8 mma, double-buffered
// cp.async.  A smem m-major stride 36, B smem k-major stride 136 (both
// conflict-free for the fragment access patterns).
#define ASZ 4608          // 128*36
#define BSZ 4352          // 32*136
#define STG 8960          // ASZ+BSZ
#define GEMM_SMEM (2*STG*4)

#define CP16(dst, src) asm volatile("cp.async.ca.shared.global [%0], [%1], 16;" :: "r"(dst), "l"(src))
#define CP16P(dst, src, sz) asm volatile("cp.async.ca.shared.global [%0], [%1], 16, %2;" :: "r"(dst), "l"(src), "r"(sz))
#define CP_COMMIT() asm volatile("cp.async.commit_group;")
#define CP_WAIT1() asm volatile("cp.async.wait_group 1;")
#define CP_WAIT0() asm volatile("cp.async.wait_group 0;")

__device__ __forceinline__ uint32_t f2tf(float x)
{
    uint32_t r;
    asm("cvt.rna.tf32.f32 %0, %1;" : "=r"(r) : "f"(x));
    return r;
}

#define MMA8(d, Ar, Br) \
    asm volatile("mma.sync.aligned.m16n8k8.row.col.f32.tf32.tf32.f32 " \
                 "{%0,%1,%2,%3},{%4,%5,%6,%7},{%8,%9},{%0,%1,%2,%3};" \
                 : "+f"((d)[0]), "+f"((d)[1]), "+f"((d)[2]), "+f"((d)[3]) \
                 : "r"((Ar)[0]), "r"((Ar)[1]), "r"((Ar)[2]), "r"((Ar)[3]), \
                   "r"((Br)[0]), "r"((Br)[1]))

__device__ __forceinline__ void compute_tile(const float* __restrict__ As,
                                             const float* __restrict__ Bs,
                                             float acc[4][4][4], int wm, int wn, int lane)
{
    const int lr = lane >> 2, lc = lane & 3;
    #pragma unroll
    for (int kk = 0; kk < 32; kk += 8) {
        uint32_t Ah[4][4], Al[4][4], Bh[4][2], Bl[4][2];
        #pragma unroll
        for (int mt = 0; mt < 4; mt++) {
            const float* ap = As + (wm * 64 + mt * 16 + lr) * 36 + kk + lc;
            float x0 = ap[0], x1 = ap[8 * 36], x2 = ap[4], x3 = ap[8 * 36 + 4];
            Ah[mt][0] = f2tf(x0); Al[mt][0] = f2tf(x0 - __uint_as_float(Ah[mt][0]));
            Ah[mt][1] = f2tf(x1); Al[mt][1] = f2tf(x1 - __uint_as_float(Ah[mt][1]));
            Ah[mt][2] = f2tf(x2); Al[mt][2] = f2tf(x2 - __uint_as_float(Ah[mt][2]));
            Ah[mt][3] = f2tf(x3); Al[mt][3] = f2tf(x3 - __uint_as_float(Ah[mt][3]));
        }
        #pragma unroll
        for (int nt = 0; nt < 4; nt++) {
            const float* bp = Bs + (kk + lc) * 136 + wn * 32 + nt * 8 + lr;
            float y0 = bp[0], y1 = bp[4 * 136];
            Bh[nt][0] = f2tf(y0); Bl[nt][0] = f2tf(y0 - __uint_as_float(Bh[nt][0]));
            Bh[nt][1] = f2tf(y1); Bl[nt][1] = f2tf(y1 - __uint_as_float(Bh[nt][1]));
        }
        #pragma unroll
        for (int mt = 0; mt < 4; mt++)
            #pragma unroll
            for (int nt = 0; nt < 4; nt++) {
                MMA8(acc[mt][nt], Ah[mt], Bh[nt]);
                MMA8(acc[mt][nt], Al[mt], Bh[nt]);
                MMA8(acc[mt][nt], Ah[mt], Bl[nt]);
            }
    }
}

__device__ __forceinline__ void gemm_epilogue(float acc[4][4][4], float* __restrict__ C,
                                              int N, int by, int bx, int wm, int wn,
                                              int lane, const float* __restrict__ bias,
                                              int relu)
{
    const int lr = lane >> 2, lc = (lane & 3) * 2;
    #pragma unroll
    for (int mt = 0; mt < 4; mt++) {
        int r0 = by * 128 + wm * 64 + mt * 16 + lr;
        #pragma unroll
        for (int nt = 0; nt < 4; nt++) {
            int c0 = bx * 128 + wn * 32 + nt * 8 + lc;
            float bx0 = 0.f, bx1 = 0.f;
            if (bias) { float2 bv = *(const float2*)(bias + c0); bx0 = bv.x; bx1 = bv.y; }
            float v0 = acc[mt][nt][0] + bx0, v1 = acc[mt][nt][1] + bx1;
            float v2 = acc[mt][nt][2] + bx0, v3 = acc[mt][nt][3] + bx1;
            if (relu) {
                v0 = fmaxf(v0, 0.f); v1 = fmaxf(v1, 0.f);
                v2 = fmaxf(v2, 0.f); v3 = fmaxf(v3, 0.f);
            }
            *(float2*)(C + (size_t)r0 * N + c0)       = make_float2(v0, v1);
            *(float2*)(C + (size_t)(r0 + 8) * N + c0) = make_float2(v2, v3);
        }
    }
}

__global__ __launch_bounds__(256) void gemm_tf32_kernel(
    const float* __restrict__ A, const float* __restrict__ B, float* __restrict__ C,
    int M, int N, int K, const float* __restrict__ bias, int relu)
{
    extern __shared__ float sm[];
    const int t = threadIdx.x;
    const int lane = t & 31, wid = t >> 5, wm = wid & 1, wn = wid >> 1;
    const int bx = blockIdx.x, by = blockIdx.y;
    const uint32_t smbase = (uint32_t)__cvta_generic_to_shared(sm);

    float acc[4][4][4];
    #pragma unroll
    for (int a = 0; a < 4; a++)
        #pragma unroll
        for (int b = 0; b < 4; b++)
            #pragma unroll
            for (int c = 0; c < 4; c++) acc[a][b][c] = 0.f;

    const int KT = K >> 5;
    auto load_tile = [&](int buf, int k0) {
        #pragma unroll
        for (int i = 0; i < 4; i++) {
            int idx = i * 256 + t;
            int m = idx >> 3, k4 = (idx & 7) << 2;
            const float* src = A + (size_t)(by * 128 + m) * K + k0 + k4;
            uint32_t dst = smbase + (uint32_t)(buf * STG + m * 36 + k4) * 4u;
            CP16(dst, src);
        }
        #pragma unroll
        for (int i = 0; i < 4; i++) {
            int idx = i * 256 + t;
            int kk = idx >> 5, n4 = (idx & 31) << 2;
            const float* src = B + (size_t)(k0 + kk) * N + bx * 128 + n4;
            uint32_t dst = smbase + (uint32_t)(buf * STG + ASZ + kk * 136 + n4) * 4u;
            CP16(dst, src);
        }
    };

    load_tile(0, 0);
    CP_COMMIT();
    for (int kt = 0; kt < KT; kt++) {
        if (kt + 1 < KT) {
            load_tile((kt + 1) & 1, (kt + 1) << 5);
            CP_COMMIT();
            CP_WAIT1();
        } else {
            CP_WAIT0();
        }
        __syncthreads();
        const float* base = sm + (kt & 1) * STG;
        compute_tile(base, base + ASZ, acc, wm, wn, lane);
        __syncthreads();
    }
    gemm_epilogue(acc, C, N, by, bx, wm, wn, lane, bias, relu);
}

// conv/deconv gather-A variant.
// mode 0 (conv k=3,p=1,s=1): tin = t + kseg - 1
// mode 1 (deconv k=3,p=1,op=s-1): tin = (t+1-kseg)/s when >=0 and divisible
__global__ __launch_bounds__(256) void convgemm_tf32_kernel(
    const float* __restrict__ In, const float* __restrict__ Wt, float* __restrict__ C,
    int Tout, int Tin, int Cin, int N, int stride, int mode,
    const float* __restrict__ bias, int relu)
{
    extern __shared__ float sm[];
    const int t = threadIdx.x;
    const int lane = t & 31, wid = t >> 5, wm = wid & 1, wn = wid >> 1;
    const int bx = blockIdx.x, by = blockIdx.y;
    const uint32_t smbase = (uint32_t)__cvta_generic_to_shared(sm);
    const int K = 3 * Cin;

    float acc[4][4][4];
    #pragma unroll
    for (int a = 0; a < 4; a++)
        #pragma unroll
        for (int b = 0; b < 4; b++)
            #pragma unroll
            for (int c = 0; c < 4; c++) acc[a][b][c] = 0.f;

    const int KT = K >> 5;
    auto load_tile = [&](int buf, int k0) {
        #pragma unroll
        for (int i = 0; i < 4; i++) {
            int idx = i * 256 + t;
            int m = idx >> 3, k4 = (idx & 7) << 2;
            int gr = by * 128 + m;
            int bb = gr / Tout, tt = gr - bb * Tout;
            int ka = k0 + k4;
            int kseg = ka / Cin, c = ka - kseg * Cin;
            const float* src = In;
            int sz = 0;
            if (mode == 0) {
                int tin = tt + kseg - 1;
                if (tin >= 0 && tin < Tin) {
                    src = In + ((size_t)(bb * Tin + tin) * Cin + c);
                    sz = 16;
                }
            } else {
                int num = tt + 1 - kseg;
                if (num >= 0 && (num % stride) == 0) {
                    int tin = num / stride;
                    if (tin < Tin) {
                        src = In + ((size_t)(bb * Tin + tin) * Cin + c);
                        sz = 16;
                    }
                }
            }
            uint32_t dst = smbase + (uint32_t)(buf * STG + m * 36 + k4) * 4u;
            CP16P(dst, src, sz);
        }
        #pragma unroll
        for (int i = 0; i < 4; i++) {
            int idx = i * 256 + t;
            int kk = idx >> 5, n4 = (idx & 31) << 2;
            const float* src = Wt + (size_t)(k0 + kk) * N + bx * 128 + n4;
            uint32_t dst = smbase + (uint32_t)(buf * STG + ASZ + kk * 136 + n4) * 4u;
            CP16(dst, src);
        }
    };

    load_tile(0, 0);
    CP_COMMIT();
    for (int kt = 0; kt < KT; kt++) {
        if (kt + 1 < KT) {
            load_tile((kt + 1) & 1, (kt + 1) << 5);
            CP_COMMIT();
            CP_WAIT1();
        } else {
            CP_WAIT0();
        }
        __syncthreads();
        const float* base = sm + (kt & 1) * STG;
        compute_tile(base, base + ASZ, acc, wm, wn, lane);
        __syncthreads();
    }
    gemm_epilogue(acc, C, N, by, bx, wm, wn, lane, bias, relu);
}

// ------------------------- fused attention (fp32, exact) --------------------
__global__ __launch_bounds__(128) void attn_kernel(
    const float* __restrict__ Q, const float* __restrict__ Kk, const float* __restrict__ V,
    float* __restrict__ O, int S, int windowed)
{
    extern __shared__ float smx[];
    float* Ks = smx;
    float* Vs = smx + 8192;
    float* Sc = smx + 16384;
    const int tid = threadIdx.x;
    const int qb = blockIdx.x, h = blockIdx.y, b = blockIdx.z;
    const int qi = qb * 128 + tid;
    const float* qp = Q + (((size_t)(b * S + qi)) * NHnum + h) * DHdim;
    float qv[64];
    #pragma unroll
    for (int d4 = 0; d4 < 16; d4++) {
        float4 v = *(const float4*)(qp + d4 * 4);
        qv[d4 * 4 + 0] = v.x; qv[d4 * 4 + 1] = v.y;
        qv[d4 * 4 + 2] = v.z; qv[d4 * 4 + 3] = v.w;
    }
    float acc[64];
    #pragma unroll
    for (int d = 0; d < 64; d++) acc[d] = 0.f;
    float mrow = -1e30f, lrow = 0.f;
    const int jb0 = windowed ? qb : 0;
    const int jb1 = windowed ? qb + 1 : (S >> 7);
    for (int jb = jb0; jb < jb1; jb++) {
        const float* kp = Kk + (((size_t)(b * S + jb * 128)) * NHnum + h) * DHdim;
        const float* vp = V  + (((size_t)(b * S + jb * 128)) * NHnum + h) * DHdim;
        #pragma unroll 4
        for (int i = tid; i < 2048; i += 128) {
            int r = i >> 4, c = i & 15;
            *(float4*)&Ks[r * 64 + c * 4] = *(const float4*)(kp + (size_t)r * Hdim + c * 4);
            *(float4*)&Vs[r * 64 + c * 4] = *(const float4*)(vp + (size_t)r * Hdim + c * 4);
        }
        __syncthreads();
        float bmax = -1e30f;
        for (int j = 0; j < 128; j++) {
            const float4* kr = (const float4*)(Ks + j * 64);
            float s0 = 0.f, s1 = 0.f, s2 = 0.f, s3 = 0.f;
            #pragma unroll
            for (int d4 = 0; d4 < 16; d4++) {
                float4 kv = kr[d4];
                s0 += qv[d4 * 4 + 0] * kv.x; s1 += qv[d4 * 4 + 1] * kv.y;
                s2 += qv[d4 * 4 + 2] * kv.z; s3 += qv[d4 * 4 + 3] * kv.w;
            }
            float sres = ((s0 + s1) + (s2 + s3)) * 0.125f;
            Sc[j * 128 + tid] = sres;
            bmax = fmaxf(bmax, sres);
        }
        float nm = fmaxf(mrow, bmax);
        float corr = __expf(mrow - nm);
        lrow *= corr;
        #pragma unroll
        for (int d = 0; d < 64; d++) acc[d] *= corr;
        for (int j = 0; j < 128; j++) {
            float p = __expf(Sc[j * 128 + tid] - nm);
            lrow += p;
            const float4* vr = (const float4*)(Vs + j * 64);
            #pragma unroll
            for (int d4 = 0; d4 < 16; d4++) {
                float4 vv = vr[d4];
                acc[d4 * 4 + 0] += p * vv.x; acc[d4 * 4 + 1] += p * vv.y;
                acc[d4 * 4 + 2] += p * vv.z; acc[d4 * 4 + 3] += p * vv.w;
            }
        }
        mrow = nm;
        __syncthreads();
    }
    const float invl = 1.f / lrow;
    float* op = O + (((size_t)(b * S + qi)) * NHnum + h) * DHdim;
    #pragma unroll
    for (int d4 = 0; d4 < 16; d4++)
        *(float4*)(op + d4 * 4) = make_float4(acc[d4 * 4 + 0] * invl, acc[d4 * 4 + 1] * invl,
                                              acc[d4 * 4 + 2] * invl, acc[d4 * 4 + 3] * invl);
}

// ------------------------- LayerNorm(in1 + in2) ------------------------------
__global__ __launch_bounds__(256) void ln_kernel(
    float* __restrict__ out, const float* __restrict__ in1, const float* __restrict__ in2,
    const float* __restrict__ g, const float* __restrict__ be)
{
    __shared__ float rs[8], rss[8];
    const int row = blockIdx.x, tid = threadIdx.x;
    const size_t base = (size_t)row * Hdim + tid * 4;
    float4 a = *(const float4*)(in1 + base);
    float4 b2 = *(const float4*)(in2 + base);
    a.x += b2.x; a.y += b2.y; a.z += b2.z; a.w += b2.w;
    float s  = a.x + a.y + a.z + a.w;
    float ss = a.x * a.x + a.y * a.y + a.z * a.z + a.w * a.w;
    #pragma unroll
    for (int o = 16; o > 0; o >>= 1) {
        s  += __shfl_xor_sync(0xffffffffu, s, o);
        ss += __shfl_xor_sync(0xffffffffu, ss, o);
    }
    if ((tid & 31) == 0) { rs[tid >> 5] = s; rss[tid >> 5] = ss; }
    __syncthreads();
    float st = 0.f, sst = 0.f;
    #pragma unroll
    for (int i = 0; i < 8; i++) { st += rs[i]; sst += rss[i]; }
    const float mean = st * (1.f / 1024.f);
    const float var  = sst * (1.f / 1024.f) - mean * mean;
    const float inv  = rsqrtf(var + 1e-5f);
    float4 gg = *(const float4*)(g + tid * 4);
    float4 bb = *(const float4*)(be + tid * 4);
    float4 o4;
    o4.x = (a.x - mean) * inv * gg.x + bb.x;
    o4.y = (a.y - mean) * inv * gg.y + bb.y;
    o4.z = (a.z - mean) * inv * gg.z + bb.z;
    o4.w = (a.w - mean) * inv * gg.w + bb.w;
    *(float4*)(out + base) = o4;
}

// ------------------------- pool / add ---------------------------------------
__global__ void poolrelu_kernel(float* __restrict__ out, const float* __restrict__ in,
                                int S2, int n4)
{
    int idx = blockIdx.x * blockDim.x + threadIdx.x;
    if (idx >= n4) return;
    int h4 = idx & 255;
    int bt = idx >> 8;
    int b = bt / S2, t2 = bt - b * S2;
    const float4* i0 = (const float4*)in + ((size_t)(b * S2 * 2 + t2 * 2) * 256 + h4);
    float4 a = i0[0], c = i0[256];
    float4 o;
    o.x = fmaxf(fmaxf(a.x, c.x), 0.f);
    o.y = fmaxf(fmaxf(a.y, c.y), 0.f);
    o.z = fmaxf(fmaxf(a.z, c.z), 0.f);
    o.w = fmaxf(fmaxf(a.w, c.w), 0.f);
    ((float4*)out)[idx] = o;
}

__global__ void add_kernel(float* __restrict__ out, const float* __restrict__ a,
                           const float* __restrict__ b, int n4)
{
    int i = blockIdx.x * blockDim.x + threadIdx.x;
    if (i >= n4) return;
    float4 x = ((const float4*)a)[i], y = ((const float4*)b)[i];
    ((float4*)out)[i] = make_float4(x.x + y.x, x.y + y.y, x.z + y.z, x.w + y.w);
}

// ------------------------- host orchestration -------------------------------
static inline void sgemm(const float* A, const float* B, float* C, int M, int N, int K,
                         const float* bias, int relu)
{
    dim3 g(N / 128, M / 128);
    gemm_tf32_kernel<<<g, 256, GEMM_SMEM>>>(A, B, C, M, N, K, bias, relu);
}

extern "C" void kernel_launch(void* const* d_in, const int* in_sizes, int n_in,
                              void* d_out, int out_size)
{
    (void)in_sizes; (void)n_in; (void)out_size;
    const float* x          = (const float*)d_in[0];
    const float* emb_w      = (const float*)d_in[1];
    const float* emb_b      = (const float*)d_in[2];
    const float* enc_qkvo   = (const float*)d_in[3];
    const float* enc_ln     = (const float*)d_in[4];
    const float* enc_ffn_w1 = (const float*)d_in[5];
    const float* enc_ffn_b1 = (const float*)d_in[6];
    const float* enc_ffn_w2 = (const float*)d_in[7];
    const float* enc_ffn_b2 = (const float*)d_in[8];
    const float* conv0_w    = (const float*)d_in[9];
    const float* conv0_b    = (const float*)d_in[10];
    const float* dec_qkvo0  = (const float*)d_in[11];
    const float* dec_ln0    = (const float*)d_in[12];
    const float* dec_attn1  = (const float*)d_in[13];
    const float* dec_attn2  = (const float*)d_in[14];
    const float* dec_ln     = (const float*)d_in[15];
    const float* dec_ffn_w1 = (const float*)d_in[16];
    const float* dec_ffn_b1 = (const float*)d_in[17];
    const float* dec_ffn_w2 = (const float*)d_in[18];
    const float* dec_ffn_b2 = (const float*)d_in[19];
    const float* dec_dw     = (const float*)d_in[20];
    const float* dec_db     = (const float*)d_in[21];

    float *xT, *wTe, *wTc, *wTd, *bX, *bQ, *bK, *bV, *bA, *bT, *bY, *bD, *bY2, *bZ, *bF;
    cudaGetSymbolAddress((void**)&xT,  g_xT);
    cudaGetSymbolAddress((void**)&wTe, g_wTe);
    cudaGetSymbolAddress((void**)&wTc, g_wTc);
    cudaGetSymbolAddress((void**)&wTd, g_wTd);
    cudaGetSymbolAddress((void**)&bX,  g_bufX);
    cudaGetSymbolAddress((void**)&bQ,  g_bufQ);
    cudaGetSymbolAddress((void**)&bK,  g_bufK);
    cudaGetSymbolAddress((void**)&bV,  g_bufV);
    cudaGetSymbolAddress((void**)&bA,  g_bufA);
    cudaGetSymbolAddress((void**)&bT,  g_bufT);
    cudaGetSymbolAddress((void**)&bY,  g_bufY);
    cudaGetSymbolAddress((void**)&bD,  g_bufD);
    cudaGetSymbolAddress((void**)&bY2, g_bufY2);
    cudaGetSymbolAddress((void**)&bZ,  g_bufZ);
    cudaGetSymbolAddress((void**)&bF,  g_bufF);

    float* out = (float*)d_out;
    float* Z0  = out;
    float* Z1  = out + (size_t)4194304;
    float* Z2  = out + (size_t)8388608;
    float* Z3  = out + (size_t)10485760;
    float* FD0 = out + (size_t)11534336;
    float* FD1 = out + (size_t)12582912;
    float* FD2 = out + (size_t)14680064;
    float* FD3 = out + (size_t)18874368;

    cudaFuncSetAttribute(attn_kernel, cudaFuncAttributeMaxDynamicSharedMemorySize, 131072);
    cudaFuncSetAttribute(gemm_tf32_kernel, cudaFuncAttributeMaxDynamicSharedMemorySize, GEMM_SMEM);
    cudaFuncSetAttribute(convgemm_tf32_kernel, cudaFuncAttributeMaxDynamicSharedMemorySize, GEMM_SMEM);

    // ---- transposes ----
    {
        dim3 blk(32, 8);
        transpose2d_kernel    <<<dim3(Tfull/32, DINc/32, Bb), blk>>>(xT, x, DINc, Tfull);
        transpose_convw_kernel<<<dim3(DINc/32, Hdim/32, 3),   blk>>>(wTe, emb_w, Hdim, DINc);
        transpose_convw_kernel<<<dim3(Hdim/32, Hdim/32, 3),   blk>>>(wTc, conv0_w, Hdim, Hdim);
        transpose_deconvw_kernel<<<(3*3*HH)/256, 256>>>(wTd, dec_dw);
    }

    // ---- embedding conv + relu: (B,T,DIN) -> bX (B,T,H) ----
    convgemm_tf32_kernel<<<dim3(Hdim/128, (Bb*Tfull)/128), 256, GEMM_SMEM>>>(
        xT, wTe, bX, Tfull, Tfull, DINc, Hdim, 1, 0, emb_b, 1);

    auto mha = [&](const float* xq, const float* xkv, const float* w, int S, int windowed) {
        int rows = Bb * S;
        sgemm(xq,  w + 0*(size_t)HH, bQ, rows, Hdim, Hdim, nullptr, 0);
        sgemm(xkv, w + 1*(size_t)HH, bK, rows, Hdim, Hdim, nullptr, 0);
        sgemm(xkv, w + 2*(size_t)HH, bV, rows, Hdim, Hdim, nullptr, 0);
        attn_kernel<<<dim3(S/128, NHnum, Bb), 128, 131072>>>(bQ, bK, bV, bA, S, windowed);
        sgemm(bA, w + 3*(size_t)HH, bT, rows, Hdim, Hdim, nullptr, 0);
    };

    // ================= encoder =================
    const int encS[4] = {1024, 1024, 512, 256};
    float* Zp[4] = {Z0, Z1, Z2, Z3};
    for (int i = 0; i < 4; i++) {
        int S = encS[i], rows = Bb * S;
        const float* w = enc_qkvo + (size_t)i * 4 * HH;
        mha(bX, bX, w, S, 1);
        const float* lnb = enc_ln + (size_t)i * 4 * Hdim;
        ln_kernel<<<rows, 256>>>(bY, bX, bT, lnb + 0*Hdim, lnb + 1*Hdim);
        sgemm(bY, enc_ffn_w1 + (size_t)i*Hdim*Ff, bF, rows, Ff, Hdim,
              enc_ffn_b1 + (size_t)i*Ff, 1);
        sgemm(bF, enc_ffn_w2 + (size_t)i*Ff*Hdim, bT, rows, Hdim, Ff,
              enc_ffn_b2 + (size_t)i*Hdim, 0);
        ln_kernel<<<rows, 256>>>(Zp[i], bY, bT, lnb + 2*Hdim, lnb + 3*Hdim);
        if (i == 0) {
            convgemm_tf32_kernel<<<dim3(Hdim/128, rows/128), 256, GEMM_SMEM>>>(
                Zp[i], wTc, bX, S, S, Hdim, Hdim, 1, 0, conv0_b, 1);
        } else if (i < 3) {
            int S2 = S / 2, n4 = Bb * S2 * (Hdim/4);
            poolrelu_kernel<<<(n4 + 255)/256, 256>>>(bX, Zp[i], S2, n4);
        }
    }

    // ================= decoder level 0 =================
    {
        int S = 256, rows = Bb * S;
        mha(Z3, Z3, dec_qkvo0, S, 0);
        ln_kernel<<<rows, 256>>>(FD0, Z3, bT, dec_ln0, dec_ln0 + Hdim);
    }

    // ================= decoder levels =================
    const float* fdPrev = FD0; int Sprev = 256;
    const float* feP[3] = {Z2, Z1, Z0};
    const int    decS[3] = {512, 1024, 1024};
    const int    decStride[3] = {2, 2, 1};
    float* fdOut[3] = {FD1, FD2, FD3};
    for (int i = 0; i < 3; i++) {
        int S = decS[i], rows = Bb * S, st = decStride[i];
        convgemm_tf32_kernel<<<dim3(Hdim/128, rows/128), 256, GEMM_SMEM>>>(
            fdPrev, wTd + (size_t)i*3*HH, bD, S, Sprev, Hdim, Hdim, st, 1,
            dec_db + (size_t)i*Hdim, 1);
        const float* a1 = dec_attn1 + (size_t)i * 4 * HH;
        const float* a2 = dec_attn2 + (size_t)i * 4 * HH;
        const float* lnb = dec_ln + (size_t)i * 6 * Hdim;
        mha(feP[i], bD, a1, S, 0);
        ln_kernel<<<rows, 256>>>(bY, feP[i], bT, lnb + 0*Hdim, lnb + 1*Hdim);
        mha(bD, feP[i], a2, S, 0);
        ln_kernel<<<rows, 256>>>(bY2, bD, bT, lnb + 2*Hdim, lnb + 3*Hdim);
        int n4 = rows * (Hdim/4);
        add_kernel<<<(n4 + 255)/256, 256>>>(bZ, bY, bY2, n4);
        sgemm(bZ, dec_ffn_w1 + (size_t)i*Hdim*Ff, bF, rows, Ff, Hdim,
              dec_ffn_b1 + (size_t)i*Ff, 1);
        sgemm(bF, dec_ffn_w2 + (size_t)i*Ff*Hdim, bT, rows, Hdim, Ff,
              dec_ffn_b2 + (size_t)i*Hdim, 0);
        ln_kernel<<<rows, 256>>>(fdOut[i], bZ, bT, lnb + 4*Hdim, lnb + 5*Hdim);
        fdPrev = fdOut[i]; Sprev = S;
    }
}